// round 4
// baseline (speedup 1.0000x reference)
#include <cuda_runtime.h>
#include <stdint.h>

// Segmented max pooling, gather formulation (CSR build + coalesced gather):
//   1) zero counts
//   2) histogram vt_map -> counts            (1M spread int atomics)
//   3) per-chunk exclusive scan              (local offsets + chunk sums)
//   4) shuffle-scan of chunk sums
//   5) cursor[i] = local_off[i] + chunksum   (cursor == global start)
//   6) fill: slot = atomicAdd(cursor) -> g_rows  (cursor ends at seg end)
//   7) gather: 1 warp/segment, start = cursor[seg]-count, unroll-4 max
// Fallback: atomic-scatter path for shapes beyond static scratch.

#define MAX_SEG   (1 << 18)   // 262144
#define MAX_ROWS  (1 << 20)   // 1048576
#define SCAN_CHUNK 1024
#define NEG_INF __int_as_float(0xff800000)

__device__ int g_counts[MAX_SEG];
__device__ int g_cursor[MAX_SEG];
__device__ int g_local[MAX_SEG];     // chunk-local exclusive offsets
__device__ int g_rows[MAX_ROWS];
__device__ int g_chunksums[1024];

// ---------------- gather path ----------------

__global__ void zero_kernel(int nseg) {
    int i = blockIdx.x * blockDim.x + threadIdx.x;
    int stride = gridDim.x * blockDim.x;
    for (; i < nseg; i += stride) g_counts[i] = 0;
}

__global__ void count_kernel(const int* __restrict__ vt_map, int n_rows, int vt_out) {
    int i = blockIdx.x * blockDim.x + threadIdx.x;
    if (i >= n_rows) return;
    int seg = vt_map[i];
    if (seg >= 0 && seg < vt_out) atomicAdd(&g_counts[seg], 1);
}

// Each block scans SCAN_CHUNK counts (4/thread), writes chunk-local exclusive
// offsets and its chunk total.
__global__ void scan_chunks_kernel(int nseg) {
    __shared__ int warp_tot[8];
    int tid = threadIdx.x;
    int lane = tid & 31;
    int wid = tid >> 5;
    int base = blockIdx.x * SCAN_CHUNK + tid * 4;
    int v[4];
    #pragma unroll
    for (int k = 0; k < 4; k++)
        v[k] = (base + k < nseg) ? g_counts[base + k] : 0;
    int tot = v[0] + v[1] + v[2] + v[3];

    // warp inclusive scan of tot
    int inc = tot;
    #pragma unroll
    for (int d = 1; d < 32; d <<= 1) {
        int t = __shfl_up_sync(0xffffffffu, inc, d);
        if (lane >= d) inc += t;
    }
    if (lane == 31) warp_tot[wid] = inc;
    __syncthreads();
    if (wid == 0) {
        int w = (lane < 8) ? warp_tot[lane] : 0;
        int wi = w;
        #pragma unroll
        for (int d = 1; d < 8; d <<= 1) {
            int t = __shfl_up_sync(0xffffffffu, wi, d);
            if (lane >= d) wi += t;
        }
        if (lane < 8) warp_tot[lane] = wi - w;   // exclusive warp prefix
    }
    __syncthreads();
    int excl = warp_tot[wid] + inc - tot;        // exclusive prefix of this thread

    int run = excl;
    #pragma unroll
    for (int k = 0; k < 4; k++) {
        if (base + k < nseg) g_local[base + k] = run;
        run += v[k];
    }
    if (tid == 255) g_chunksums[blockIdx.x] = warp_tot[7] + inc;  // chunk total
}

// Exclusive scan of up to 1024 chunk sums; shuffle-based, 1024 threads.
__global__ void scan_sums_kernel(int nchunks) {
    __shared__ int warp_tot[32];
    int tid = threadIdx.x;
    int lane = tid & 31;
    int wid = tid >> 5;
    int v = (tid < nchunks) ? g_chunksums[tid] : 0;
    int inc = v;
    #pragma unroll
    for (int d = 1; d < 32; d <<= 1) {
        int t = __shfl_up_sync(0xffffffffu, inc, d);
        if (lane >= d) inc += t;
    }
    if (lane == 31) warp_tot[wid] = inc;
    __syncthreads();
    if (wid == 0) {
        int w = warp_tot[lane];
        int wi = w;
        #pragma unroll
        for (int d = 1; d < 32; d <<= 1) {
            int t = __shfl_up_sync(0xffffffffu, wi, d);
            if (lane >= d) wi += t;
        }
        warp_tot[lane] = wi - w;
    }
    __syncthreads();
    if (tid < nchunks) g_chunksums[tid] = warp_tot[wid] + inc - v;  // exclusive
}

// cursor[i] = global start offset of segment i
__global__ void cursor_init_kernel(int nseg) {
    int i = blockIdx.x * blockDim.x + threadIdx.x;
    int stride = gridDim.x * blockDim.x;
    for (; i < nseg; i += stride)
        g_cursor[i] = g_local[i] + g_chunksums[i >> 10];
}

__global__ void fill_kernel(const int* __restrict__ vt_map, int n_rows, int vt_out) {
    int i = blockIdx.x * blockDim.x + threadIdx.x;
    if (i >= n_rows) return;
    int seg = vt_map[i];
    if (seg >= 0 && seg < vt_out) {
        int pos = atomicAdd(&g_cursor[seg], 1);
        g_rows[pos] = i;
    }
}

// One warp per segment; C == 64: lane holds channels {2l, 2l+1} as float2.
// After fill, cursor[seg] == end; start = end - count.
__global__ void gather_max_kernel(const float2* __restrict__ in2,
                                  float2* __restrict__ out2, int nseg) {
    int warp = (blockIdx.x * blockDim.x + threadIdx.x) >> 5;
    int lane = threadIdx.x & 31;
    if (warp >= nseg) return;
    int cnt = g_counts[warp];
    int off = g_cursor[warp] - cnt;
    float2 acc = make_float2(NEG_INF, NEG_INF);
    int j = 0;
    for (; j + 4 <= cnt; j += 4) {
        int r0 = __ldg(&g_rows[off + j]);
        int r1 = __ldg(&g_rows[off + j + 1]);
        int r2 = __ldg(&g_rows[off + j + 2]);
        int r3 = __ldg(&g_rows[off + j + 3]);
        float2 a = __ldg(&in2[(size_t)r0 * 32 + lane]);
        float2 b = __ldg(&in2[(size_t)r1 * 32 + lane]);
        float2 c = __ldg(&in2[(size_t)r2 * 32 + lane]);
        float2 d = __ldg(&in2[(size_t)r3 * 32 + lane]);
        acc.x = fmaxf(acc.x, fmaxf(fmaxf(a.x, b.x), fmaxf(c.x, d.x)));
        acc.y = fmaxf(acc.y, fmaxf(fmaxf(a.y, b.y), fmaxf(c.y, d.y)));
    }
    for (; j < cnt; j++) {
        int r0 = __ldg(&g_rows[off + j]);
        float2 a = __ldg(&in2[(size_t)r0 * 32 + lane]);
        acc.x = fmaxf(acc.x, a.x);
        acc.y = fmaxf(acc.y, a.y);
    }
    if (cnt == 0) acc = make_float2(0.0f, 0.0f);
    out2[(size_t)warp * 32 + lane] = acc;
}

// ---------------- fallback scatter path (generic) ----------------

__device__ __forceinline__ unsigned fkey(float f) {
    unsigned b = __float_as_uint(f);
    return (b & 0x80000000u) ? ~b : (b | 0x80000000u);
}
__device__ __forceinline__ float fdecode(unsigned k) {
    unsigned b = (k & 0x80000000u) ? (k & 0x7FFFFFFFu) : ~k;
    return __uint_as_float(b);
}
#define INIT_KEY 0x007FFFFFu

__global__ void init_out_kernel(unsigned* out, long n) {
    long i = blockIdx.x * (long)blockDim.x + threadIdx.x;
    long stride = gridDim.x * (long)blockDim.x;
    for (; i < n; i += stride) out[i] = INIT_KEY;
}

__global__ void scatter_max_kernel(const float* __restrict__ in,
                                   const int* __restrict__ vt_map,
                                   unsigned* __restrict__ out,
                                   long n_total, int C, int vt_out) {
    long i = blockIdx.x * (long)blockDim.x + threadIdx.x;
    long stride = gridDim.x * (long)blockDim.x;
    for (; i < n_total; i += stride) {
        long row = i / C;
        int  c   = (int)(i - row * C);
        int seg = vt_map[row];
        if (seg < 0 || seg >= vt_out) continue;
        atomicMax(out + (size_t)seg * C + c, fkey(in[i]));
    }
}

__global__ void fixup_kernel(unsigned* __restrict__ out, long n) {
    long i = blockIdx.x * (long)blockDim.x + threadIdx.x;
    long stride = gridDim.x * (long)blockDim.x;
    for (; i < n; i += stride) {
        unsigned k = out[i];
        float f = (k == INIT_KEY) ? 0.0f : fdecode(k);
        out[i] = __float_as_uint(f);
    }
}

// ---------------- launcher ----------------

extern "C" void kernel_launch(void* const* d_in, const int* in_sizes, int n_in,
                              void* d_out, int out_size) {
    const float* inputs = (const float*)d_in[0];
    // d_in[1] = vt_replace (unused for max pooling)
    const int*   vt_map = (const int*)d_in[2];

    long n_in_elems = in_sizes[0];                 // N_IN * C
    int  n_rows     = in_sizes[2];                 // N_IN
    int  C          = (int)(n_in_elems / n_rows);  // 64
    int  vt_out     = out_size / C;                // 262144

    const int TPB = 256;

    if (C == 64 && vt_out <= MAX_SEG && n_rows <= MAX_ROWS) {
        int nseg = vt_out;
        int nchunks = (nseg + SCAN_CHUNK - 1) / SCAN_CHUNK;   // 256 here

        zero_kernel<<<1024, TPB>>>(nseg);
        count_kernel<<<(n_rows + TPB - 1) / TPB, TPB>>>(vt_map, n_rows, vt_out);
        scan_chunks_kernel<<<nchunks, 256>>>(nseg);
        scan_sums_kernel<<<1, 1024>>>(nchunks);
        cursor_init_kernel<<<1024, TPB>>>(nseg);
        fill_kernel<<<(n_rows + TPB - 1) / TPB, TPB>>>(vt_map, n_rows, vt_out);

        int warps_per_block = TPB / 32;
        int gblocks = (nseg + warps_per_block - 1) / warps_per_block;
        gather_max_kernel<<<gblocks, TPB>>>((const float2*)inputs,
                                            (float2*)d_out, nseg);
    } else {
        long out_elems = (long)out_size;
        int blocks = 148 * 16;
        init_out_kernel<<<blocks, TPB>>>((unsigned*)d_out, out_elems);
        scatter_max_kernel<<<blocks * 2, TPB>>>(inputs, vt_map,
                                                (unsigned*)d_out, n_in_elems, C, vt_out);
        fixup_kernel<<<blocks, TPB>>>((unsigned*)d_out, out_elems);
    }
}

// round 5
// speedup vs baseline: 1.4825x; 1.4825x over previous
#include <cuda_runtime.h>
#include <stdint.h>

// Segmented max pooling — bucketed gather, single-pass CSR substitute:
//   1) zero counts + spill counter
//   2) fill: pos = atomicAdd(count[seg]); pos<CAP -> bucket, else spill list
//   3) gather: 1 warp/segment, max over bucket rows (C=64: float2/lane)
//   4) spill: CAS-float-max for overflow rows (statistically empty, required
//      for correctness)
// Fallback: generic atomic-scatter path for shapes beyond static scratch.

#define MAX_SEG   (1 << 18)   // 262144
#define MAX_ROWS  (1 << 20)   // 1048576
#define CAP        32
#define NEG_INF __int_as_float(0xff800000)

__device__ int g_counts[MAX_SEG];
__device__ int g_bucket[MAX_SEG * CAP];   // 32 MB scratch
__device__ int g_spill_rows[MAX_ROWS];
__device__ int g_spill_n;

// ---------------- bucketed gather path ----------------

__global__ void zero_kernel(int nseg) {
    int i = blockIdx.x * blockDim.x + threadIdx.x;
    int stride = gridDim.x * blockDim.x;
    for (; i < nseg; i += stride) g_counts[i] = 0;
    if (blockIdx.x == 0 && threadIdx.x == 0) g_spill_n = 0;
}

__global__ void fill_kernel(const int* __restrict__ vt_map, int n_rows, int vt_out) {
    int i = blockIdx.x * blockDim.x + threadIdx.x;
    if (i >= n_rows) return;
    int seg = vt_map[i];
    if (seg < 0 || seg >= vt_out) return;
    int pos = atomicAdd(&g_counts[seg], 1);
    if (pos < CAP) {
        g_bucket[(size_t)seg * CAP + pos] = i;
    } else {
        int s = atomicAdd(&g_spill_n, 1);
        g_spill_rows[s] = i;
    }
}

// One warp per segment; C == 64: lane holds channels {2l, 2l+1} as float2.
__global__ void gather_max_kernel(const float2* __restrict__ in2,
                                  float2* __restrict__ out2, int nseg) {
    int warp = (blockIdx.x * blockDim.x + threadIdx.x) >> 5;
    int lane = threadIdx.x & 31;
    if (warp >= nseg) return;
    int cnt = g_counts[warp];
    int use = cnt < CAP ? cnt : CAP;
    const int* __restrict__ bkt = g_bucket + (size_t)warp * CAP;
    float2 acc = make_float2(NEG_INF, NEG_INF);
    int j = 0;
    for (; j + 4 <= use; j += 4) {
        int r0 = __ldg(&bkt[j]);
        int r1 = __ldg(&bkt[j + 1]);
        int r2 = __ldg(&bkt[j + 2]);
        int r3 = __ldg(&bkt[j + 3]);
        float2 a = __ldg(&in2[(size_t)r0 * 32 + lane]);
        float2 b = __ldg(&in2[(size_t)r1 * 32 + lane]);
        float2 c = __ldg(&in2[(size_t)r2 * 32 + lane]);
        float2 d = __ldg(&in2[(size_t)r3 * 32 + lane]);
        acc.x = fmaxf(fmaxf(acc.x, fmaxf(a.x, b.x)), fmaxf(c.x, d.x));
        acc.y = fmaxf(fmaxf(acc.y, fmaxf(a.y, b.y)), fmaxf(c.y, d.y));
    }
    if (j + 2 <= use) {
        int r0 = __ldg(&bkt[j]);
        int r1 = __ldg(&bkt[j + 1]);
        float2 a = __ldg(&in2[(size_t)r0 * 32 + lane]);
        float2 b = __ldg(&in2[(size_t)r1 * 32 + lane]);
        acc.x = fmaxf(acc.x, fmaxf(a.x, b.x));
        acc.y = fmaxf(acc.y, fmaxf(a.y, b.y));
        j += 2;
    }
    if (j < use) {
        int r0 = __ldg(&bkt[j]);
        float2 a = __ldg(&in2[(size_t)r0 * 32 + lane]);
        acc.x = fmaxf(acc.x, a.x);
        acc.y = fmaxf(acc.y, a.y);
    }
    if (cnt == 0) acc = make_float2(0.0f, 0.0f);
    out2[(size_t)warp * 32 + lane] = acc;
}

__device__ __forceinline__ void atomicMaxFloat(float* addr, float v) {
    int* a = (int*)addr;
    int cur = *a;
    while (__int_as_float(cur) < v) {
        int prev = atomicCAS(a, cur, __float_as_int(v));
        if (prev == cur) break;
        cur = prev;
    }
}

// Handle bucket overflow rows (expected 0 entries; correctness safety net).
// One warp per spilled row; lane covers channels {2l, 2l+1}.
__global__ void spill_kernel(const float* __restrict__ in,
                             const int* __restrict__ vt_map,
                             float* __restrict__ out) {
    int n = g_spill_n;
    int nwarps = (gridDim.x * blockDim.x) >> 5;
    int warp = (blockIdx.x * blockDim.x + threadIdx.x) >> 5;
    int lane = threadIdx.x & 31;
    for (int e = warp; e < n; e += nwarps) {
        int row = g_spill_rows[e];
        int seg = vt_map[row];
        const float* src = in + (size_t)row * 64;
        float* dst = out + (size_t)seg * 64;
        atomicMaxFloat(dst + 2 * lane,     src[2 * lane]);
        atomicMaxFloat(dst + 2 * lane + 1, src[2 * lane + 1]);
    }
}

// ---------------- fallback scatter path (generic) ----------------

__device__ __forceinline__ unsigned fkey(float f) {
    unsigned b = __float_as_uint(f);
    return (b & 0x80000000u) ? ~b : (b | 0x80000000u);
}
__device__ __forceinline__ float fdecode(unsigned k) {
    unsigned b = (k & 0x80000000u) ? (k & 0x7FFFFFFFu) : ~k;
    return __uint_as_float(b);
}
#define INIT_KEY 0x007FFFFFu

__global__ void init_out_kernel(unsigned* out, long n) {
    long i = blockIdx.x * (long)blockDim.x + threadIdx.x;
    long stride = gridDim.x * (long)blockDim.x;
    for (; i < n; i += stride) out[i] = INIT_KEY;
}

__global__ void scatter_max_kernel(const float* __restrict__ in,
                                   const int* __restrict__ vt_map,
                                   unsigned* __restrict__ out,
                                   long n_total, int C, int vt_out) {
    long i = blockIdx.x * (long)blockDim.x + threadIdx.x;
    long stride = gridDim.x * (long)blockDim.x;
    for (; i < n_total; i += stride) {
        long row = i / C;
        int  c   = (int)(i - row * C);
        int seg = vt_map[row];
        if (seg < 0 || seg >= vt_out) continue;
        atomicMax(out + (size_t)seg * C + c, fkey(in[i]));
    }
}

__global__ void fixup_kernel(unsigned* __restrict__ out, long n) {
    long i = blockIdx.x * (long)blockDim.x + threadIdx.x;
    long stride = gridDim.x * (long)blockDim.x;
    for (; i < n; i += stride) {
        unsigned k = out[i];
        float f = (k == INIT_KEY) ? 0.0f : fdecode(k);
        out[i] = __float_as_uint(f);
    }
}

// ---------------- launcher ----------------

extern "C" void kernel_launch(void* const* d_in, const int* in_sizes, int n_in,
                              void* d_out, int out_size) {
    const float* inputs = (const float*)d_in[0];
    // d_in[1] = vt_replace (unused for max pooling)
    const int*   vt_map = (const int*)d_in[2];

    long n_in_elems = in_sizes[0];                 // N_IN * C
    int  n_rows     = in_sizes[2];                 // N_IN
    int  C          = (int)(n_in_elems / n_rows);  // 64
    int  vt_out     = out_size / C;                // 262144

    const int TPB = 256;

    if (C == 64 && vt_out <= MAX_SEG && n_rows <= MAX_ROWS) {
        int nseg = vt_out;

        zero_kernel<<<512, TPB>>>(nseg);
        fill_kernel<<<(n_rows + TPB - 1) / TPB, TPB>>>(vt_map, n_rows, vt_out);

        int warps_per_block = TPB / 32;
        int gblocks = (nseg + warps_per_block - 1) / warps_per_block;
        gather_max_kernel<<<gblocks, TPB>>>((const float2*)inputs,
                                            (float2*)d_out, nseg);
        spill_kernel<<<64, TPB>>>(inputs, vt_map, (float*)d_out);
    } else {
        long out_elems = (long)out_size;
        int blocks = 148 * 16;
        init_out_kernel<<<blocks, TPB>>>((unsigned*)d_out, out_elems);
        scatter_max_kernel<<<blocks * 2, TPB>>>(inputs, vt_map,
                                                (unsigned*)d_out, n_in_elems, C, vt_out);
        fixup_kernel<<<blocks, TPB>>>((unsigned*)d_out, out_elems);
    }
}